// round 13
// baseline (speedup 1.0000x reference)
#include <cuda_runtime.h>
#include <cuda_fp16.h>
#include <math.h>
#include <stdint.h>

// ---------------------------------------------------------------------------
// Problem constants
// ---------------------------------------------------------------------------
#define BB 8
#define SS 1024
#define EE 1024
#define HH 16
#define HD 64
#define FFD 4096
#define MM (BB * SS)                 // 8192 rows
#define SCALE 1.7328679513998633f    // sqrt(1/64) * 2 * ln(1024)
#define SCALE_L2E (SCALE * 1.4426950408889634f)   // logits in log2 domain

#define PERSIST_GRID 296             // 148 SMs x 2 CTAs
#define ATT_GRID 444                 // 148 SMs x 3 CTAs

// ---------------------------------------------------------------------------
// PTX helpers (base sm_103 target: HMMA mma.sync + ldmatrix + cp.async)
// ---------------------------------------------------------------------------
__device__ __forceinline__ uint32_t smem_u32(const void* p) {
    uint32_t a;
    asm("{ .reg .u64 t; cvta.to.shared.u64 t, %1; cvt.u32.u64 %0, t; }"
        : "=r"(a) : "l"(p));
    return a;
}

#define CP_ASYNC16(dst, src) \
    asm volatile("cp.async.cg.shared.global [%0], [%1], 16;\n" \
                 :: "r"(dst), "l"(src))
#define CP_COMMIT() asm volatile("cp.async.commit_group;\n" ::: "memory")
#define CP_WAIT0()  asm volatile("cp.async.wait_group 0;\n" ::: "memory")
#define CP_WAIT1()  asm volatile("cp.async.wait_group 1;\n" ::: "memory")

__device__ __forceinline__ void ldsm4(uint32_t* r, uint32_t addr) {
    asm volatile("ldmatrix.sync.aligned.m8n8.x4.shared.b16 {%0,%1,%2,%3}, [%4];\n"
                 : "=r"(r[0]), "=r"(r[1]), "=r"(r[2]), "=r"(r[3]) : "r"(addr));
}
__device__ __forceinline__ void ldsm4t(uint32_t* r, uint32_t addr) {
    asm volatile("ldmatrix.sync.aligned.m8n8.x4.trans.shared.b16 {%0,%1,%2,%3}, [%4];\n"
                 : "=r"(r[0]), "=r"(r[1]), "=r"(r[2]), "=r"(r[3]) : "r"(addr));
}

__device__ __forceinline__ void mma_f16(float* d, const uint32_t* a,
                                        const uint32_t* b) {
    asm volatile(
        "mma.sync.aligned.m16n8k16.row.col.f32.f16.f16.f32 "
        "{%0,%1,%2,%3}, {%4,%5,%6,%7}, {%8,%9}, {%0,%1,%2,%3};\n"
        : "+f"(d[0]), "+f"(d[1]), "+f"(d[2]), "+f"(d[3])
        : "r"(a[0]), "r"(a[1]), "r"(a[2]), "r"(a[3]), "r"(b[0]), "r"(b[1]));
}

__device__ __forceinline__ float ex2(float x) {
    float r;
    asm("ex2.approx.f32 %0, %1;" : "=f"(r) : "f"(x));
    return r;
}

__device__ __forceinline__ void split2(float v0, float v1,
                                       uint32_t& hp, uint32_t& lp) {
    __half h0 = __float2half_rn(v0);
    __half h1 = __float2half_rn(v1);
    __half l0 = __float2half_rn(v0 - __half2float(h0));
    __half l1 = __float2half_rn(v1 - __half2float(h1));
    hp = (uint32_t)__half_as_ushort(h0) | ((uint32_t)__half_as_ushort(h1) << 16);
    lp = (uint32_t)__half_as_ushort(l0) | ((uint32_t)__half_as_ushort(l1) << 16);
}
__device__ __forceinline__ uint32_t pack2(float v0, float v1) {
    return (uint32_t)__half_as_ushort(__float2half_rn(v0))
         | ((uint32_t)__half_as_ushort(__float2half_rn(v1)) << 16);
}

// ---------------------------------------------------------------------------
// Scratch (device globals)
// ---------------------------------------------------------------------------
__device__ float g_attnout[(size_t)MM * EE];
__device__ float g_h1[(size_t)MM * EE];
__device__ float g_ff2[(size_t)MM * EE];
__device__ __half g_qkvh[(size_t)MM * 3 * EE], g_qkvl[(size_t)MM * 3 * EE];
__device__ __half g_xh[(size_t)MM * EE],  g_xl[(size_t)MM * EE];
__device__ __half g_ctxh[(size_t)MM * EE];
__device__ __half g_h1h[(size_t)MM * EE];
__device__ __half g_ff1h[(size_t)MM * FFD];
__device__ __half g_wqkvh[(size_t)3 * EE * EE], g_wqkvl[(size_t)3 * EE * EE];
__device__ __half g_wout[(size_t)EE * EE];
__device__ __half g_w1[(size_t)FFD * EE];
__device__ __half g_w2[(size_t)EE * FFD];

// ---------------------------------------------------------------------------
// fp32 -> f16 (hi, lo) split (8 elems/thread)
// ---------------------------------------------------------------------------
__global__ void split_fp32(const float* __restrict__ in,
                           __half* __restrict__ hi,
                           __half* __restrict__ lo, int n, float scale)
{
    int i = (blockIdx.x * blockDim.x + threadIdx.x) * 8;
    if (i >= n) return;
    float4 v0 = *(const float4*)(in + i);
    float4 v1 = *(const float4*)(in + i + 4);
    uint32_t hp[4], lp[4];
    split2(v0.x * scale, v0.y * scale, hp[0], lp[0]);
    split2(v0.z * scale, v0.w * scale, hp[1], lp[1]);
    split2(v1.x * scale, v1.y * scale, hp[2], lp[2]);
    split2(v1.z * scale, v1.w * scale, hp[3], lp[3]);
    *(uint4*)(hi + i) = make_uint4(hp[0], hp[1], hp[2], hp[3]);
    *(uint4*)(lo + i) = make_uint4(lp[0], lp[1], lp[2], lp[3]);
}

// Wq rows get SCALE*log2e (softmax computed in log2 domain); Wk, Wv get 1.0
__global__ void split_wqkv(const float* __restrict__ in,
                           __half* __restrict__ hi,
                           __half* __restrict__ lo, int n)
{
    int i = (blockIdx.x * blockDim.x + threadIdx.x) * 8;
    if (i >= n) return;
    float scale = (i < EE * EE) ? SCALE_L2E : 1.0f;
    float4 v0 = *(const float4*)(in + i);
    float4 v1 = *(const float4*)(in + i + 4);
    uint32_t hp[4], lp[4];
    split2(v0.x * scale, v0.y * scale, hp[0], lp[0]);
    split2(v0.z * scale, v0.w * scale, hp[1], lp[1]);
    split2(v1.x * scale, v1.y * scale, hp[2], lp[2]);
    split2(v1.z * scale, v1.w * scale, hp[3], lp[3]);
    *(uint4*)(hi + i) = make_uint4(hp[0], hp[1], hp[2], hp[3]);
    *(uint4*)(lo + i) = make_uint4(lp[0], lp[1], lp[2], lp[3]);
}

__global__ void conv3_fp32(const float* __restrict__ a, __half* __restrict__ oa, int na,
                           const float* __restrict__ b, __half* __restrict__ ob, int nb,
                           const float* __restrict__ c, __half* __restrict__ oc, int nc)
{
    int i = (blockIdx.x * blockDim.x + threadIdx.x) * 8;
    const float* src; __half* dst; int j;
    if (i < na)            { src = a; dst = oa; j = i; }
    else if (i < na + nb)  { src = b; dst = ob; j = i - na; }
    else if (i < na + nb + nc) { src = c; dst = oc; j = i - na - nb; }
    else return;
    float4 v0 = *(const float4*)(src + j);
    float4 v1 = *(const float4*)(src + j + 4);
    *(uint4*)(dst + j) = make_uint4(pack2(v0.x, v0.y), pack2(v0.z, v0.w),
                                    pack2(v1.x, v1.y), pack2(v1.z, v1.w));
}

// ---------------------------------------------------------------------------
// Dedicated QK projection kernel (3-term f16, near-exact).  (Round-10 form.)
// BM=128, BN=64, BK=64, 2-stage double buffer, 8 warps (32x32 each),
// smem 96 KB -> 2 CTAs/SM (16 warps) for latency hiding.
// ---------------------------------------------------------------------------
#define QK_A_BYTES 16384              // 128 rows x 128 B
#define QK_B_BYTES 8192               // 64 rows x 128 B
#define QK_STAGE (2 * QK_A_BYTES + 2 * QK_B_BYTES)   // 49152
#define SMEMB_QK (2 * QK_STAGE)       // 98304

__global__ void __launch_bounds__(256, 2) gemm_qk(
    const __half* __restrict__ Ah, const __half* __restrict__ Al,
    const __half* __restrict__ Bh, const __half* __restrict__ Bl,
    __half* __restrict__ Chi, __half* __restrict__ Clo,
    int Nstride, int K)
{
    extern __shared__ __align__(128) char smem[];
    const uint32_t sb = smem_u32(smem);
    const int tid = threadIdx.x;
    const int lane = tid & 31, wid = tid >> 5;
    const int warpM = wid & 3, warpN = wid >> 2;   // 4 x 2 warps
    const int bm = blockIdx.y * 128, bn = blockIdx.x * 64;

    const __half* aSrc[2] = { Ah + (size_t)bm * K, Al + (size_t)bm * K };
    const __half* bSrc[2] = { Bh + (size_t)bn * K, Bl + (size_t)bn * K };

    const int lrow = tid >> 3;      // 0..31
    const int lcol = tid & 7;

    const int arow = lane & 15;
    const int akh  = lane >> 4;
    const int brow = ((lane >> 4) << 3) + (lane & 7);
    const int bkh  = (lane >> 3) & 1;

    float acc[2][4][4] = {};
    const int nk = K >> 6;          // 16

    auto issue_stage = [&](int kt, int buf) {
        const uint32_t dbase = sb + buf * QK_STAGE;
#pragma unroll
        for (int t = 0; t < 2; t++) {
            const __half* s0 = aSrc[t] + kt * 64 + lcol * 8;
#pragma unroll
            for (int p = 0; p < 4; p++) {
                int row = lrow + p * 32;
                uint32_t dst = dbase + t * QK_A_BYTES + row * 128
                             + ((lcol ^ (row & 7)) << 4);
                CP_ASYNC16(dst, s0 + (size_t)row * K);
            }
        }
#pragma unroll
        for (int t = 0; t < 2; t++) {
            const __half* s0 = bSrc[t] + kt * 64 + lcol * 8;
#pragma unroll
            for (int p = 0; p < 2; p++) {
                int row = lrow + p * 32;
                uint32_t dst = dbase + 2 * QK_A_BYTES + t * QK_B_BYTES + row * 128
                             + ((lcol ^ (row & 7)) << 4);
                CP_ASYNC16(dst, s0 + (size_t)row * K);
            }
        }
    };

    issue_stage(0, 0); CP_COMMIT();
    issue_stage(1, 1); CP_COMMIT();

    for (int kt = 0; kt < nk; kt++) {
        const int buf = kt & 1;
        CP_WAIT1();
        __syncthreads();

        const uint32_t st = sb + buf * QK_STAGE;
#pragma unroll
        for (int ks = 0; ks < 4; ks++) {
            uint32_t af[2][2][4];
            uint32_t bfr[2][2][4];
#pragma unroll
            for (int hl = 0; hl < 2; hl++)
#pragma unroll
                for (int mt = 0; mt < 2; mt++) {
                    int row = warpM * 32 + mt * 16 + arow;
                    uint32_t a = st + hl * QK_A_BYTES + row * 128
                               + (((ks * 2 + akh) ^ (arow & 7)) << 4);
                    ldsm4(af[hl][mt], a);
                }
#pragma unroll
            for (int hl = 0; hl < 2; hl++)
#pragma unroll
                for (int nt2 = 0; nt2 < 2; nt2++) {
                    int row = warpN * 32 + nt2 * 16 + brow;
                    uint32_t a = st + 2 * QK_A_BYTES + hl * QK_B_BYTES + row * 128
                               + (((ks * 2 + bkh) ^ (brow & 7)) << 4);
                    ldsm4(bfr[hl][nt2], a);
                }
#pragma unroll
            for (int mt = 0; mt < 2; mt++)
#pragma unroll
                for (int ntp = 0; ntp < 2; ntp++) {
                    float* a0 = acc[mt][2 * ntp];
                    float* a1 = acc[mt][2 * ntp + 1];
                    mma_f16(a0, af[0][mt], &bfr[0][ntp][0]);
                    mma_f16(a1, af[0][mt], &bfr[0][ntp][2]);
                    mma_f16(a0, af[1][mt], &bfr[0][ntp][0]);
                    mma_f16(a1, af[1][mt], &bfr[0][ntp][2]);
                    mma_f16(a0, af[0][mt], &bfr[1][ntp][0]);
                    mma_f16(a1, af[0][mt], &bfr[1][ntp][2]);
                }
        }
        __syncthreads();
        if (kt + 2 < nk) { issue_stage(kt + 2, buf); }
        CP_COMMIT();
    }

    const int N = Nstride;
#pragma unroll
    for (int mt = 0; mt < 2; mt++) {
        const int r0 = bm + warpM * 32 + mt * 16 + (lane >> 2);
#pragma unroll
        for (int nt = 0; nt < 4; nt++) {
            const int col = bn + warpN * 32 + nt * 8 + (lane & 3) * 2;
            uint32_t hp, lp;
            split2(acc[mt][nt][0], acc[mt][nt][1], hp, lp);
            *(uint32_t*)(Chi + (size_t)r0 * N + col) = hp;
            *(uint32_t*)(Clo + (size_t)r0 * N + col) = lp;
            split2(acc[mt][nt][2], acc[mt][nt][3], hp, lp);
            *(uint32_t*)(Chi + (size_t)(r0 + 8) * N + col) = hp;
            *(uint32_t*)(Clo + (size_t)(r0 + 8) * N + col) = lp;
        }
    }
}

// ---------------------------------------------------------------------------
// HMMA f16 GEMM (single-term), PERSISTENT: grid-stride loop over output tiles.
// 128x128 CTA tile, BK=64, 3-stage cp.async pipeline, 8 warps (32x64 each).
// EPI: 0 = fp32 out, 1 = bias+relu -> f16 hi, 2 = bias -> fp32, 4 = f16 hi
// ---------------------------------------------------------------------------
#define TILE_BYTES 16384
#define GEMM_STAGES 3

template <int EPI>
__global__ void __launch_bounds__(256, 2) gemm_hmma(
    const __half* __restrict__ Ah,
    const __half* __restrict__ Bh,
    const float* __restrict__ bias, float* __restrict__ Cf,
    __half* __restrict__ Chi,
    int Nstride, int K, int tilesX, int tilesTotal)
{
    constexpr int STAGE_BYTES = 2 * TILE_BYTES;
    extern __shared__ __align__(128) char smem[];
    const uint32_t sb = smem_u32(smem);
    const int tid = threadIdx.x;
    const int lane = tid & 31, wid = tid >> 5;
    const int warpM = wid & 3, warpN = wid >> 2;

    const int lrow = tid >> 3;
    const int lcol = tid & 7;

    const int arow = lane & 15;
    const int akh  = lane >> 4;
    const int brow = ((lane >> 4) << 3) + (lane & 7);
    const int bkh  = (lane >> 3) & 1;

    const int nk = K >> 6;
    const int N = Nstride;

    for (int item = blockIdx.x; item < tilesTotal; item += gridDim.x) {
        const int bm = (item / tilesX) * 128;
        const int bn = (item % tilesX) * 128;
        const __half* srcs[2] = { Ah + (size_t)bm * K, Bh + (size_t)bn * K };

        float acc[2][8][4] = {};

        auto issue_stage = [&](int kt, int buf) {
            const uint32_t dbase = sb + buf * STAGE_BYTES;
#pragma unroll
            for (int t = 0; t < 2; t++) {
                const __half* s0 = srcs[t] + kt * 64 + lcol * 8;
#pragma unroll
                for (int p = 0; p < 4; p++) {
                    int row = lrow + p * 32;
                    uint32_t dst = dbase + t * TILE_BYTES + row * 128
                                 + ((lcol ^ (row & 7)) << 4);
                    CP_ASYNC16(dst, s0 + (size_t)row * K);
                }
            }
        };

        issue_stage(0, 0); CP_COMMIT();
        issue_stage(1, 1); CP_COMMIT();

        for (int kt = 0; kt < nk; kt++) {
            const int buf = kt % GEMM_STAGES;
            CP_WAIT1();
            __syncthreads();
            if (kt + 2 < nk) { issue_stage(kt + 2, (kt + 2) % GEMM_STAGES); }
            CP_COMMIT();

            const uint32_t st = sb + buf * STAGE_BYTES;
#pragma unroll
            for (int ks = 0; ks < 4; ks++) {
                uint32_t af[2][4];
                uint32_t bfr[4][4];
#pragma unroll
                for (int mt = 0; mt < 2; mt++) {
                    int row = warpM * 32 + mt * 16 + arow;
                    uint32_t a = st + row * 128
                               + (((ks * 2 + akh) ^ (arow & 7)) << 4);
                    ldsm4(af[mt], a);
                }
#pragma unroll
                for (int nt2 = 0; nt2 < 4; nt2++) {
                    int row = warpN * 64 + nt2 * 16 + brow;
                    uint32_t a = st + TILE_BYTES + row * 128
                               + (((ks * 2 + bkh) ^ (brow & 7)) << 4);
                    ldsm4(bfr[nt2], a);
                }
#pragma unroll
                for (int mt = 0; mt < 2; mt++)
#pragma unroll
                    for (int nt = 0; nt < 8; nt++) {
                        const uint32_t* b0 = &bfr[nt >> 1][(nt & 1) * 2];
                        mma_f16(acc[mt][nt], af[mt], b0);
                    }
            }
            __syncthreads();
        }

#pragma unroll
        for (int mt = 0; mt < 2; mt++) {
            const int r0 = bm + warpM * 32 + mt * 16 + (lane >> 2);
#pragma unroll
            for (int nt = 0; nt < 8; nt++) {
                const int col = bn + warpN * 64 + nt * 8 + (lane & 3) * 2;
                float d0 = acc[mt][nt][0], d1 = acc[mt][nt][1];
                float d2 = acc[mt][nt][2], d3 = acc[mt][nt][3];
                if (EPI == 1 || EPI == 2) {
                    float b0v = bias[col], b1v = bias[col + 1];
                    d0 += b0v; d1 += b1v; d2 += b0v; d3 += b1v;
                }
                if (EPI == 1) {
                    d0 = fmaxf(d0, 0.f); d1 = fmaxf(d1, 0.f);
                    d2 = fmaxf(d2, 0.f); d3 = fmaxf(d3, 0.f);
                    *(uint32_t*)(Chi + (size_t)r0 * N + col) = pack2(d0, d1);
                    *(uint32_t*)(Chi + (size_t)(r0 + 8) * N + col) = pack2(d2, d3);
                } else if (EPI == 4) {
                    *(uint32_t*)(Chi + (size_t)r0 * N + col) = pack2(d0, d1);
                    *(uint32_t*)(Chi + (size_t)(r0 + 8) * N + col) = pack2(d2, d3);
                } else {
                    *(float2*)(Cf + (size_t)r0 * N + col) = make_float2(d0, d1);
                    *(float2*)(Cf + (size_t)(r0 + 8) * N + col) = make_float2(d2, d3);
                }
            }
        }
        __syncthreads();   // smem safe for next item's loads
    }
}

// ---------------------------------------------------------------------------
// HMMA flash attention (f16x3 QK^T, f16x1 PV, fp32 softmax in log2 domain).
// PERSISTENT: grid-stride loop over (q-tile, bh) work items.
// Block: 128 threads (4 warps), 64-query tile of one (b,h).
// smem: Q hi/lo (16 KB) + 2 stages x (Kh,Kl,Vh) (48 KB) = 64 KB.
// ---------------------------------------------------------------------------
#define ATT_STAGE 24576
#define SMEMB_ATT (16384 + 2 * ATT_STAGE)
#define ATT_ITEMS ((SS / 64) * BB * HH)   // 2048

__global__ void __launch_bounds__(128) flash_attn_hmma(
    const __half* __restrict__ qkvh, const __half* __restrict__ qkvl,
    __half* __restrict__ ctxh)
{
    extern __shared__ __align__(128) char sm[];
    const uint32_t sb = smem_u32(sm);
    const uint32_t qb = sb;
    const uint32_t kvb = sb + 16384;
    const int tid = threadIdx.x, lane = tid & 31, w = tid >> 5;

    const int lrow = tid >> 1;
    const int lc0 = (tid & 1) * 4;

    const int arow = lane & 15, akh = lane >> 4;
    const int brow = ((lane >> 4) << 3) + (lane & 7);
    const int bkh  = (lane >> 3) & 1;
    const int vkey_off = ((lane >> 3) & 1) * 8 + (lane & 7);
    const int vchk_off = lane >> 4;
    const int nkt = SS / 64;

    for (int item = blockIdx.x; item < ATT_ITEMS; item += gridDim.x) {
        const int q0 = (item & 15) * 64;
        const int bh = item >> 4;
        const int b = bh >> 4, h = bh & 15;
        const size_t rowbase = (size_t)b * SS;

        // ---- Q load ----
        {
            const __half* sh = qkvh + (rowbase + q0 + lrow) * (3 * EE) + h * HD + lc0 * 8;
            const __half* sl = qkvl + (rowbase + q0 + lrow) * (3 * EE) + h * HD + lc0 * 8;
#pragma unroll
            for (int c = 0; c < 4; c++) {
                uint32_t d = qb + lrow * 128 + (((lc0 + c) ^ (lrow & 7)) << 4);
                CP_ASYNC16(d, sh + c * 8);
                CP_ASYNC16(d + 8192, sl + c * 8);
            }
        }
        CP_COMMIT();

        auto load_kv = [&](int kt, int buf) {
            size_t grow = (rowbase + kt * 64 + lrow) * (3 * EE);
            const __half* kh = qkvh + grow + EE + h * HD + lc0 * 8;
            const __half* kl = qkvl + grow + EE + h * HD + lc0 * 8;
            const __half* vh = qkvh + grow + 2 * EE + h * HD + lc0 * 8;
            uint32_t d = kvb + buf * ATT_STAGE + lrow * 128;
#pragma unroll
            for (int c = 0; c < 4; c++) {
                uint32_t sw = (((lc0 + c) ^ (lrow & 7)) << 4);
                CP_ASYNC16(d + sw, kh + c * 8);
                CP_ASYNC16(d + 8192 + sw, kl + c * 8);
                CP_ASYNC16(d + 16384 + sw, vh + c * 8);
            }
        };
        load_kv(0, 0); CP_COMMIT();
        CP_WAIT0();
        __syncthreads();

        // ---- Q fragments (resident) ----
        uint32_t qa[2][4][4];
#pragma unroll
        for (int hl = 0; hl < 2; hl++)
#pragma unroll
            for (int kb = 0; kb < 4; kb++) {
                int row = w * 16 + arow;
                uint32_t a = qb + hl * 8192 + row * 128
                           + (((kb * 2 + akh) ^ (row & 7)) << 4);
                ldsm4(qa[hl][kb], a);
            }

        float o[8][4] = {};
        float m0 = -1e30f, m1 = -1e30f, l0 = 0.f, l1 = 0.f;

        for (int kt = 0; kt < nkt; kt++) {
            const int buf = kt & 1;
            if (kt + 1 < nkt) load_kv(kt + 1, buf ^ 1);
            CP_COMMIT();
            const uint32_t stb = kvb + buf * ATT_STAGE;

            float sf[8][4] = {};
#pragma unroll
            for (int np = 0; np < 4; np++) {
                int rowb = np * 16 + brow;
#pragma unroll
                for (int kb = 0; kb < 4; kb++) {
                    uint32_t kfh[4], kfl[4];
                    uint32_t sw = (((kb * 2 + bkh) ^ (rowb & 7)) << 4);
                    ldsm4(kfh, stb + rowb * 128 + sw);
                    ldsm4(kfl, stb + 8192 + rowb * 128 + sw);
#pragma unroll
                    for (int e = 0; e < 2; e++) {
                        float* d = sf[2 * np + e];
                        mma_f16(d, qa[0][kb], &kfh[e * 2]);
                        mma_f16(d, qa[0][kb], &kfl[e * 2]);
                        mma_f16(d, qa[1][kb], &kfh[e * 2]);
                    }
                }
            }

            // online softmax (log2 domain)
            float mx0 = m0, mx1 = m1;
#pragma unroll
            for (int nt = 0; nt < 8; nt++) {
                mx0 = fmaxf(mx0, fmaxf(sf[nt][0], sf[nt][1]));
                mx1 = fmaxf(mx1, fmaxf(sf[nt][2], sf[nt][3]));
            }
            mx0 = fmaxf(mx0, __shfl_xor_sync(0xffffffffu, mx0, 1));
            mx0 = fmaxf(mx0, __shfl_xor_sync(0xffffffffu, mx0, 2));
            mx1 = fmaxf(mx1, __shfl_xor_sync(0xffffffffu, mx1, 1));
            mx1 = fmaxf(mx1, __shfl_xor_sync(0xffffffffu, mx1, 2));
            float corr0 = ex2(m0 - mx0), corr1 = ex2(m1 - mx1);
            m0 = mx0; m1 = mx1;

            float rs0 = 0.f, rs1 = 0.f;
#pragma unroll
            for (int nt = 0; nt < 8; nt++) {
                sf[nt][0] = ex2(sf[nt][0] - m0);
                sf[nt][1] = ex2(sf[nt][1] - m0);
                sf[nt][2] = ex2(sf[nt][2] - m1);
                sf[nt][3] = ex2(sf[nt][3] - m1);
                rs0 += sf[nt][0] + sf[nt][1];
                rs1 += sf[nt][2] + sf[nt][3];
            }
            rs0 += __shfl_xor_sync(0xffffffffu, rs0, 1);
            rs0 += __shfl_xor_sync(0xffffffffu, rs0, 2);
            rs1 += __shfl_xor_sync(0xffffffffu, rs1, 1);
            rs1 += __shfl_xor_sync(0xffffffffu, rs1, 2);
            l0 = l0 * corr0 + rs0;
            l1 = l1 * corr1 + rs1;
#pragma unroll
            for (int nt = 0; nt < 8; nt++) {
                o[nt][0] *= corr0; o[nt][1] *= corr0;
                o[nt][2] *= corr1; o[nt][3] *= corr1;
            }

#pragma unroll
            for (int kb2 = 0; kb2 < 4; kb2++) {
                uint32_t pah[4];
                pah[0] = pack2(sf[2 * kb2][0],     sf[2 * kb2][1]);
                pah[1] = pack2(sf[2 * kb2][2],     sf[2 * kb2][3]);
                pah[2] = pack2(sf[2 * kb2 + 1][0], sf[2 * kb2 + 1][1]);
                pah[3] = pack2(sf[2 * kb2 + 1][2], sf[2 * kb2 + 1][3]);
                int vkey = kb2 * 16 + vkey_off;
#pragma unroll
                for (int np = 0; np < 4; np++) {
                    uint32_t vfh[4];
                    uint32_t sw = (((np * 2 + vchk_off) ^ (vkey & 7)) << 4);
                    ldsm4t(vfh, stb + 16384 + vkey * 128 + sw);
                    mma_f16(o[2 * np],     pah, &vfh[0]);
                    mma_f16(o[2 * np + 1], pah, &vfh[2]);
                }
            }

            CP_WAIT0();
            __syncthreads();
        }

        const float inv0 = 1.f / l0, inv1 = 1.f / l1;
        const size_t r0 = rowbase + q0 + w * 16 + (lane >> 2);
        const int colb = h * HD + (lane & 3) * 2;
#pragma unroll
        for (int nt = 0; nt < 8; nt++) {
            *(uint32_t*)(ctxh + r0 * EE + colb + nt * 8) =
                pack2(o[nt][0] * inv0, o[nt][1] * inv0);
            *(uint32_t*)(ctxh + (r0 + 8) * EE + colb + nt * 8) =
                pack2(o[nt][2] * inv1, o[nt][3] * inv1);
        }
        __syncthreads();   // smem safe for next item's loads
    }
}

// ---------------------------------------------------------------------------
// Fused residual add + LayerNorm (+ optional f16 output)
// ---------------------------------------------------------------------------
template <int SPLIT>
__global__ void __launch_bounds__(256) add_ln_kernel(
    const float* __restrict__ X, const float* __restrict__ R,
    const float* __restrict__ gam, const float* __restrict__ bet,
    float* __restrict__ out, __half* __restrict__ ohi)
{
    __shared__ float red[8][2];
    __shared__ float s_mu, s_rstd;

    const int row = blockIdx.x;
    const int t = threadIdx.x;
    const size_t base = (size_t)row * EE + t * 4;

    float4 xv = *(const float4*)(X + base);
    float4 rv = *(const float4*)(R + base);
    float v0 = xv.x + rv.x, v1 = xv.y + rv.y;
    float v2 = xv.z + rv.z, v3 = xv.w + rv.w;

    float s  = v0 + v1 + v2 + v3;
    float ss = v0 * v0 + v1 * v1 + v2 * v2 + v3 * v3;
#pragma unroll
    for (int o = 16; o; o >>= 1) {
        s  += __shfl_down_sync(0xffffffffu, s, o);
        ss += __shfl_down_sync(0xffffffffu, ss, o);
    }
    if ((t & 31) == 0) { red[t >> 5][0] = s; red[t >> 5][1] = ss; }
    __syncthreads();
    if (t == 0) {
        float S = 0.f, SSum = 0.f;
#pragma unroll
        for (int i = 0; i < 8; i++) { S += red[i][0]; SSum += red[i][1]; }
        float mu = S * (1.f / EE);
        float var = SSum * (1.f / EE) - mu * mu;
        s_mu = mu;
        s_rstd = rsqrtf(var + 1e-5f);
    }
    __syncthreads();
    const float mu = s_mu, rstd = s_rstd;

    float4 gv = *(const float4*)(gam + t * 4);
    float4 bv = *(const float4*)(bet + t * 4);
    float o0 = (v0 - mu) * rstd * gv.x + bv.x;
    float o1 = (v1 - mu) * rstd * gv.y + bv.y;
    float o2 = (v2 - mu) * rstd * gv.z + bv.z;
    float o3 = (v3 - mu) * rstd * gv.w + bv.w;
    *(float4*)(out + base) = make_float4(o0, o1, o2, o3);

    if (SPLIT) {
        *(uint2*)(ohi + base) = make_uint2(pack2(o0, o1), pack2(o2, o3));
    }
}

// ---------------------------------------------------------------------------
// Launch
// ---------------------------------------------------------------------------
extern "C" void kernel_launch(void* const* d_in, const int* in_sizes, int n_in,
                              void* d_out, int out_size)
{
    const float* x          = (const float*)d_in[0];
    const float* in_proj_w  = (const float*)d_in[1];
    const float* out_proj_w = (const float*)d_in[2];
    const float* ln1_g      = (const float*)d_in[3];
    const float* ln1_b      = (const float*)d_in[4];
    const float* ln2_g      = (const float*)d_in[5];
    const float* ln2_b      = (const float*)d_in[6];
    const float* w1         = (const float*)d_in[7];
    const float* b1         = (const float*)d_in[8];
    const float* w2         = (const float*)d_in[9];
    const float* b2         = (const float*)d_in[10];
    float* out = (float*)d_out;

    float *attnout, *h1, *ff2;
    __half *qkvh, *qkvl, *xh, *xl, *ctxh, *h1h, *ff1h;
    __half *wqkvh, *wqkvl, *wout, *w1c, *w2c;
    cudaGetSymbolAddress((void**)&attnout, g_attnout);
    cudaGetSymbolAddress((void**)&h1,      g_h1);
    cudaGetSymbolAddress((void**)&ff2,     g_ff2);
    cudaGetSymbolAddress((void**)&qkvh,    g_qkvh);
    cudaGetSymbolAddress((void**)&qkvl,    g_qkvl);
    cudaGetSymbolAddress((void**)&xh,      g_xh);
    cudaGetSymbolAddress((void**)&xl,      g_xl);
    cudaGetSymbolAddress((void**)&ctxh,    g_ctxh);
    cudaGetSymbolAddress((void**)&h1h,     g_h1h);
    cudaGetSymbolAddress((void**)&ff1h,    g_ff1h);
    cudaGetSymbolAddress((void**)&wqkvh,   g_wqkvh);
    cudaGetSymbolAddress((void**)&wqkvl,   g_wqkvl);
    cudaGetSymbolAddress((void**)&wout,    g_wout);
    cudaGetSymbolAddress((void**)&w1c,     g_w1);
    cudaGetSymbolAddress((void**)&w2c,     g_w2);

    const int SMEM1 = 2 * 3 * TILE_BYTES;   // 96 KB
    cudaFuncSetAttribute(gemm_qk, cudaFuncAttributeMaxDynamicSharedMemorySize, SMEMB_QK);
    cudaFuncSetAttribute(gemm_hmma<4>, cudaFuncAttributeMaxDynamicSharedMemorySize, SMEM1);
    cudaFuncSetAttribute(gemm_hmma<0>, cudaFuncAttributeMaxDynamicSharedMemorySize, SMEM1);
    cudaFuncSetAttribute(gemm_hmma<1>, cudaFuncAttributeMaxDynamicSharedMemorySize, SMEM1);
    cudaFuncSetAttribute(gemm_hmma<2>, cudaFuncAttributeMaxDynamicSharedMemorySize, SMEM1);
    cudaFuncSetAttribute(flash_attn_hmma, cudaFuncAttributeMaxDynamicSharedMemorySize, SMEMB_ATT);

    dim3 blk(256);

    // --- precision conversions ---
    split_fp32<<<(MM * EE / 8 + 255) / 256, blk>>>(x, xh, xl, MM * EE, 1.f);
    split_wqkv<<<(3 * EE * EE / 8 + 255) / 256, blk>>>(in_proj_w, wqkvh, wqkvl, 3 * EE * EE);
    conv3_fp32<<<((EE * EE + FFD * EE + EE * FFD) / 8 + 255) / 256, blk>>>(
        out_proj_w, wout, EE * EE, w1, w1c, FFD * EE, w2, w2c, EE * FFD);

    // 1a) QK projection (3-term, 2 CTAs/SM) -> f16 hi/lo
    gemm_qk<<<dim3(2 * EE / 64, MM / 128), blk, SMEMB_QK>>>(
        xh, xl, wqkvh, wqkvl, qkvh, qkvl, 3 * EE, EE);
    // 1b) V projection (1-term, persistent) -> f16 hi, cols [2E, 3E)
    gemm_hmma<4><<<PERSIST_GRID, blk, SMEM1>>>(
        xh, wqkvh + (size_t)2 * EE * EE, nullptr, nullptr,
        qkvh + 2 * EE, 3 * EE, EE, EE / 128, (EE / 128) * (MM / 128));
    // 2) attention (HMMA, persistent) -> ctx f16
    flash_attn_hmma<<<ATT_GRID, 128, SMEMB_ATT>>>(qkvh, qkvl, ctxh);
    // 3) out projection (1-term, persistent) -> fp32
    gemm_hmma<0><<<PERSIST_GRID, blk, SMEM1>>>(
        ctxh, wout, nullptr, attnout, nullptr, EE, EE,
        EE / 128, (EE / 128) * (MM / 128));
    // 4) h1 = LN(x + attnout) -> fp32 + f16
    add_ln_kernel<1><<<MM, blk>>>(x, attnout, ln1_g, ln1_b, h1, h1h);
    // 5) ff1 = relu(h1 @ w1^T + b1) (1-term, persistent) -> f16
    gemm_hmma<1><<<PERSIST_GRID, blk, SMEM1>>>(
        h1h, w1c, b1, nullptr, ff1h, FFD, EE,
        FFD / 128, (FFD / 128) * (MM / 128));
    // 6) ff2 = ff1 @ w2^T + b2 (1-term, persistent) -> fp32
    gemm_hmma<2><<<PERSIST_GRID, blk, SMEM1>>>(
        ff1h, w2c, b2, ff2, nullptr, EE, FFD,
        EE / 128, (EE / 128) * (MM / 128));
    // 7) out = LN(h1 + ff2)
    add_ln_kernel<0><<<MM, blk>>>(h1, ff2, ln2_g, ln2_b, out, nullptr);
}

// round 14
// speedup vs baseline: 1.0708x; 1.0708x over previous
#include <cuda_runtime.h>
#include <cuda_fp16.h>
#include <math.h>
#include <stdint.h>

// ---------------------------------------------------------------------------
// Problem constants
// ---------------------------------------------------------------------------
#define BB 8
#define SS 1024
#define EE 1024
#define HH 16
#define HD 64
#define FFD 4096
#define MM (BB * SS)                 // 8192 rows
#define SCALE 1.7328679513998633f    // sqrt(1/64) * 2 * ln(1024)
#define SCALE_L2E (SCALE * 1.4426950408889634f)   // logits in log2 domain

// ---------------------------------------------------------------------------
// PTX helpers (base sm_103 target: HMMA mma.sync + ldmatrix + cp.async)
// ---------------------------------------------------------------------------
__device__ __forceinline__ uint32_t smem_u32(const void* p) {
    uint32_t a;
    asm("{ .reg .u64 t; cvta.to.shared.u64 t, %1; cvt.u32.u64 %0, t; }"
        : "=r"(a) : "l"(p));
    return a;
}

#define CP_ASYNC16(dst, src) \
    asm volatile("cp.async.cg.shared.global [%0], [%1], 16;\n" \
                 :: "r"(dst), "l"(src))
#define CP_COMMIT() asm volatile("cp.async.commit_group;\n" ::: "memory")
#define CP_WAIT0()  asm volatile("cp.async.wait_group 0;\n" ::: "memory")
#define CP_WAIT1()  asm volatile("cp.async.wait_group 1;\n" ::: "memory")

__device__ __forceinline__ void ldsm4(uint32_t* r, uint32_t addr) {
    asm volatile("ldmatrix.sync.aligned.m8n8.x4.shared.b16 {%0,%1,%2,%3}, [%4];\n"
                 : "=r"(r[0]), "=r"(r[1]), "=r"(r[2]), "=r"(r[3]) : "r"(addr));
}
__device__ __forceinline__ void ldsm4t(uint32_t* r, uint32_t addr) {
    asm volatile("ldmatrix.sync.aligned.m8n8.x4.trans.shared.b16 {%0,%1,%2,%3}, [%4];\n"
                 : "=r"(r[0]), "=r"(r[1]), "=r"(r[2]), "=r"(r[3]) : "r"(addr));
}

__device__ __forceinline__ void mma_f16(float* d, const uint32_t* a,
                                        const uint32_t* b) {
    asm volatile(
        "mma.sync.aligned.m16n8k16.row.col.f32.f16.f16.f32 "
        "{%0,%1,%2,%3}, {%4,%5,%6,%7}, {%8,%9}, {%0,%1,%2,%3};\n"
        : "+f"(d[0]), "+f"(d[1]), "+f"(d[2]), "+f"(d[3])
        : "r"(a[0]), "r"(a[1]), "r"(a[2]), "r"(a[3]), "r"(b[0]), "r"(b[1]));
}

__device__ __forceinline__ float ex2(float x) {
    float r;
    asm("ex2.approx.f32 %0, %1;" : "=f"(r) : "f"(x));
    return r;
}
// pack two f32 -> f16x2 (lo = v0, hi = v1)
__device__ __forceinline__ uint32_t cvt_f16x2(float v0, float v1) {
    uint32_t d;
    asm("cvt.rn.f16x2.f32 %0, %1, %2;" : "=r"(d) : "f"(v1), "f"(v0));
    return d;
}
// elementwise 2^x on packed f16x2
__device__ __forceinline__ uint32_t ex2_f16x2(uint32_t x) {
    uint32_t d;
    asm("ex2.approx.f16x2 %0, %1;" : "=r"(d) : "r"(x));
    return d;
}
__device__ __forceinline__ uint32_t hadd2u(uint32_t a, uint32_t b) {
    uint32_t d;
    asm("add.f16x2 %0, %1, %2;" : "=r"(d) : "r"(a), "r"(b));
    return d;
}

__device__ __forceinline__ void split2(float v0, float v1,
                                       uint32_t& hp, uint32_t& lp) {
    __half h0 = __float2half_rn(v0);
    __half h1 = __float2half_rn(v1);
    __half l0 = __float2half_rn(v0 - __half2float(h0));
    __half l1 = __float2half_rn(v1 - __half2float(h1));
    hp = (uint32_t)__half_as_ushort(h0) | ((uint32_t)__half_as_ushort(h1) << 16);
    lp = (uint32_t)__half_as_ushort(l0) | ((uint32_t)__half_as_ushort(l1) << 16);
}
__device__ __forceinline__ uint32_t pack2(float v0, float v1) {
    return (uint32_t)__half_as_ushort(__float2half_rn(v0))
         | ((uint32_t)__half_as_ushort(__float2half_rn(v1)) << 16);
}

// ---------------------------------------------------------------------------
// Scratch (device globals)
// ---------------------------------------------------------------------------
__device__ float g_attnout[(size_t)MM * EE];
__device__ float g_h1[(size_t)MM * EE];
__device__ float g_ff2[(size_t)MM * EE];
__device__ __half g_qkvh[(size_t)MM * 3 * EE], g_qkvl[(size_t)MM * 3 * EE];
__device__ __half g_xh[(size_t)MM * EE],  g_xl[(size_t)MM * EE];
__device__ __half g_ctxh[(size_t)MM * EE];
__device__ __half g_h1h[(size_t)MM * EE];
__device__ __half g_ff1h[(size_t)MM * FFD];
__device__ __half g_wqkvh[(size_t)3 * EE * EE], g_wqkvl[(size_t)3 * EE * EE];
__device__ __half g_wout[(size_t)EE * EE];
__device__ __half g_w1[(size_t)FFD * EE];
__device__ __half g_w2[(size_t)EE * FFD];

// ---------------------------------------------------------------------------
// fp32 -> f16 (hi, lo) split (8 elems/thread)
// ---------------------------------------------------------------------------
__global__ void split_fp32(const float* __restrict__ in,
                           __half* __restrict__ hi,
                           __half* __restrict__ lo, int n, float scale)
{
    int i = (blockIdx.x * blockDim.x + threadIdx.x) * 8;
    if (i >= n) return;
    float4 v0 = *(const float4*)(in + i);
    float4 v1 = *(const float4*)(in + i + 4);
    uint32_t hp[4], lp[4];
    split2(v0.x * scale, v0.y * scale, hp[0], lp[0]);
    split2(v0.z * scale, v0.w * scale, hp[1], lp[1]);
    split2(v1.x * scale, v1.y * scale, hp[2], lp[2]);
    split2(v1.z * scale, v1.w * scale, hp[3], lp[3]);
    *(uint4*)(hi + i) = make_uint4(hp[0], hp[1], hp[2], hp[3]);
    *(uint4*)(lo + i) = make_uint4(lp[0], lp[1], lp[2], lp[3]);
}

// Wq rows get SCALE*log2e (softmax computed in log2 domain); Wk, Wv get 1.0
__global__ void split_wqkv(const float* __restrict__ in,
                           __half* __restrict__ hi,
                           __half* __restrict__ lo, int n)
{
    int i = (blockIdx.x * blockDim.x + threadIdx.x) * 8;
    if (i >= n) return;
    float scale = (i < EE * EE) ? SCALE_L2E : 1.0f;
    float4 v0 = *(const float4*)(in + i);
    float4 v1 = *(const float4*)(in + i + 4);
    uint32_t hp[4], lp[4];
    split2(v0.x * scale, v0.y * scale, hp[0], lp[0]);
    split2(v0.z * scale, v0.w * scale, hp[1], lp[1]);
    split2(v1.x * scale, v1.y * scale, hp[2], lp[2]);
    split2(v1.z * scale, v1.w * scale, hp[3], lp[3]);
    *(uint4*)(hi + i) = make_uint4(hp[0], hp[1], hp[2], hp[3]);
    *(uint4*)(lo + i) = make_uint4(lp[0], lp[1], lp[2], lp[3]);
}

__global__ void conv3_fp32(const float* __restrict__ a, __half* __restrict__ oa, int na,
                           const float* __restrict__ b, __half* __restrict__ ob, int nb,
                           const float* __restrict__ c, __half* __restrict__ oc, int nc)
{
    int i = (blockIdx.x * blockDim.x + threadIdx.x) * 8;
    const float* src; __half* dst; int j;
    if (i < na)            { src = a; dst = oa; j = i; }
    else if (i < na + nb)  { src = b; dst = ob; j = i - na; }
    else if (i < na + nb + nc) { src = c; dst = oc; j = i - na - nb; }
    else return;
    float4 v0 = *(const float4*)(src + j);
    float4 v1 = *(const float4*)(src + j + 4);
    *(uint4*)(dst + j) = make_uint4(pack2(v0.x, v0.y), pack2(v0.z, v0.w),
                                    pack2(v1.x, v1.y), pack2(v1.z, v1.w));
}

// ---------------------------------------------------------------------------
// Dedicated QK projection kernel (3-term f16, near-exact).  (Round-10 form.)
// BM=128, BN=64, BK=64, 2-stage double buffer, 8 warps (32x32 each),
// smem 96 KB -> 2 CTAs/SM (16 warps) for latency hiding.
// ---------------------------------------------------------------------------
#define QK_A_BYTES 16384              // 128 rows x 128 B
#define QK_B_BYTES 8192               // 64 rows x 128 B
#define QK_STAGE (2 * QK_A_BYTES + 2 * QK_B_BYTES)   // 49152
#define SMEMB_QK (2 * QK_STAGE)       // 98304

__global__ void __launch_bounds__(256, 2) gemm_qk(
    const __half* __restrict__ Ah, const __half* __restrict__ Al,
    const __half* __restrict__ Bh, const __half* __restrict__ Bl,
    __half* __restrict__ Chi, __half* __restrict__ Clo,
    int Nstride, int K)
{
    extern __shared__ __align__(128) char smem[];
    const uint32_t sb = smem_u32(smem);
    const int tid = threadIdx.x;
    const int lane = tid & 31, wid = tid >> 5;
    const int warpM = wid & 3, warpN = wid >> 2;   // 4 x 2 warps
    const int bm = blockIdx.y * 128, bn = blockIdx.x * 64;

    const __half* aSrc[2] = { Ah + (size_t)bm * K, Al + (size_t)bm * K };
    const __half* bSrc[2] = { Bh + (size_t)bn * K, Bl + (size_t)bn * K };

    const int lrow = tid >> 3;      // 0..31
    const int lcol = tid & 7;

    const int arow = lane & 15;
    const int akh  = lane >> 4;
    const int brow = ((lane >> 4) << 3) + (lane & 7);
    const int bkh  = (lane >> 3) & 1;

    float acc[2][4][4] = {};
    const int nk = K >> 6;          // 16

    auto issue_stage = [&](int kt, int buf) {
        const uint32_t dbase = sb + buf * QK_STAGE;
#pragma unroll
        for (int t = 0; t < 2; t++) {
            const __half* s0 = aSrc[t] + kt * 64 + lcol * 8;
#pragma unroll
            for (int p = 0; p < 4; p++) {
                int row = lrow + p * 32;
                uint32_t dst = dbase + t * QK_A_BYTES + row * 128
                             + ((lcol ^ (row & 7)) << 4);
                CP_ASYNC16(dst, s0 + (size_t)row * K);
            }
        }
#pragma unroll
        for (int t = 0; t < 2; t++) {
            const __half* s0 = bSrc[t] + kt * 64 + lcol * 8;
#pragma unroll
            for (int p = 0; p < 2; p++) {
                int row = lrow + p * 32;
                uint32_t dst = dbase + 2 * QK_A_BYTES + t * QK_B_BYTES + row * 128
                             + ((lcol ^ (row & 7)) << 4);
                CP_ASYNC16(dst, s0 + (size_t)row * K);
            }
        }
    };

    issue_stage(0, 0); CP_COMMIT();
    issue_stage(1, 1); CP_COMMIT();

    for (int kt = 0; kt < nk; kt++) {
        const int buf = kt & 1;
        CP_WAIT1();
        __syncthreads();

        const uint32_t st = sb + buf * QK_STAGE;
#pragma unroll
        for (int ks = 0; ks < 4; ks++) {
            uint32_t af[2][2][4];
            uint32_t bfr[2][2][4];
#pragma unroll
            for (int hl = 0; hl < 2; hl++)
#pragma unroll
                for (int mt = 0; mt < 2; mt++) {
                    int row = warpM * 32 + mt * 16 + arow;
                    uint32_t a = st + hl * QK_A_BYTES + row * 128
                               + (((ks * 2 + akh) ^ (arow & 7)) << 4);
                    ldsm4(af[hl][mt], a);
                }
#pragma unroll
            for (int hl = 0; hl < 2; hl++)
#pragma unroll
                for (int nt2 = 0; nt2 < 2; nt2++) {
                    int row = warpN * 32 + nt2 * 16 + brow;
                    uint32_t a = st + 2 * QK_A_BYTES + hl * QK_B_BYTES + row * 128
                               + (((ks * 2 + bkh) ^ (brow & 7)) << 4);
                    ldsm4(bfr[hl][nt2], a);
                }
#pragma unroll
            for (int mt = 0; mt < 2; mt++)
#pragma unroll
                for (int ntp = 0; ntp < 2; ntp++) {
                    float* a0 = acc[mt][2 * ntp];
                    float* a1 = acc[mt][2 * ntp + 1];
                    mma_f16(a0, af[0][mt], &bfr[0][ntp][0]);
                    mma_f16(a1, af[0][mt], &bfr[0][ntp][2]);
                    mma_f16(a0, af[1][mt], &bfr[0][ntp][0]);
                    mma_f16(a1, af[1][mt], &bfr[0][ntp][2]);
                    mma_f16(a0, af[0][mt], &bfr[1][ntp][0]);
                    mma_f16(a1, af[0][mt], &bfr[1][ntp][2]);
                }
        }
        __syncthreads();
        if (kt + 2 < nk) { issue_stage(kt + 2, buf); }
        CP_COMMIT();
    }

    const int N = Nstride;
#pragma unroll
    for (int mt = 0; mt < 2; mt++) {
        const int r0 = bm + warpM * 32 + mt * 16 + (lane >> 2);
#pragma unroll
        for (int nt = 0; nt < 4; nt++) {
            const int col = bn + warpN * 32 + nt * 8 + (lane & 3) * 2;
            uint32_t hp, lp;
            split2(acc[mt][nt][0], acc[mt][nt][1], hp, lp);
            *(uint32_t*)(Chi + (size_t)r0 * N + col) = hp;
            *(uint32_t*)(Clo + (size_t)r0 * N + col) = lp;
            split2(acc[mt][nt][2], acc[mt][nt][3], hp, lp);
            *(uint32_t*)(Chi + (size_t)(r0 + 8) * N + col) = hp;
            *(uint32_t*)(Clo + (size_t)(r0 + 8) * N + col) = lp;
        }
    }
}

// ---------------------------------------------------------------------------
// HMMA f16 GEMM (single-term): C[M,N] = A[M,K] * B[N,K]^T
// 128x128 CTA tile, BK=64, 3-stage cp.async pipeline, 8 warps (32x64 each).
// EPI: 0 = fp32 out, 1 = bias+relu -> f16 hi, 2 = bias -> fp32, 4 = f16 hi
// ---------------------------------------------------------------------------
#define TILE_BYTES 16384
#define GEMM_STAGES 3

template <int EPI>
__global__ void __launch_bounds__(256, 2) gemm_hmma(
    const __half* __restrict__ Ah,
    const __half* __restrict__ Bh,
    const float* __restrict__ bias, float* __restrict__ Cf,
    __half* __restrict__ Chi,
    int Nstride, int K)
{
    constexpr int STAGE_BYTES = 2 * TILE_BYTES;
    extern __shared__ __align__(128) char smem[];
    const uint32_t sb = smem_u32(smem);
    const int tid = threadIdx.x;
    const int lane = tid & 31, wid = tid >> 5;
    const int warpM = wid & 3, warpN = wid >> 2;
    const int bm = blockIdx.y * 128, bn = blockIdx.x * 128;

    const __half* srcs[2] = { Ah + (size_t)bm * K, Bh + (size_t)bn * K };

    const int lrow = tid >> 3;
    const int lcol = tid & 7;

    const int arow = lane & 15;
    const int akh  = lane >> 4;
    const int brow = ((lane >> 4) << 3) + (lane & 7);
    const int bkh  = (lane >> 3) & 1;

    float acc[2][8][4] = {};
    const int nk = K >> 6;

    auto issue_stage = [&](int kt, int buf) {
        const uint32_t dbase = sb + buf * STAGE_BYTES;
#pragma unroll
        for (int t = 0; t < 2; t++) {
            const __half* s0 = srcs[t] + kt * 64 + lcol * 8;
#pragma unroll
            for (int p = 0; p < 4; p++) {
                int row = lrow + p * 32;
                uint32_t dst = dbase + t * TILE_BYTES + row * 128
                             + ((lcol ^ (row & 7)) << 4);
                CP_ASYNC16(dst, s0 + (size_t)row * K);
            }
        }
    };

    issue_stage(0, 0); CP_COMMIT();
    issue_stage(1, 1); CP_COMMIT();

    for (int kt = 0; kt < nk; kt++) {
        const int buf = kt % GEMM_STAGES;
        CP_WAIT1();
        __syncthreads();
        if (kt + 2 < nk) { issue_stage(kt + 2, (kt + 2) % GEMM_STAGES); }
        CP_COMMIT();

        const uint32_t st = sb + buf * STAGE_BYTES;
#pragma unroll
        for (int ks = 0; ks < 4; ks++) {
            uint32_t af[2][4];
            uint32_t bfr[4][4];
#pragma unroll
            for (int mt = 0; mt < 2; mt++) {
                int row = warpM * 32 + mt * 16 + arow;
                uint32_t a = st + row * 128
                           + (((ks * 2 + akh) ^ (arow & 7)) << 4);
                ldsm4(af[mt], a);
            }
#pragma unroll
            for (int nt2 = 0; nt2 < 4; nt2++) {
                int row = warpN * 64 + nt2 * 16 + brow;
                uint32_t a = st + TILE_BYTES + row * 128
                           + (((ks * 2 + bkh) ^ (brow & 7)) << 4);
                ldsm4(bfr[nt2], a);
            }
#pragma unroll
            for (int mt = 0; mt < 2; mt++)
#pragma unroll
                for (int nt = 0; nt < 8; nt++) {
                    const uint32_t* b0 = &bfr[nt >> 1][(nt & 1) * 2];
                    mma_f16(acc[mt][nt], af[mt], b0);
                }
        }
        __syncthreads();
    }

    const int N = Nstride;
#pragma unroll
    for (int mt = 0; mt < 2; mt++) {
        const int r0 = bm + warpM * 32 + mt * 16 + (lane >> 2);
#pragma unroll
        for (int nt = 0; nt < 8; nt++) {
            const int col = bn + warpN * 64 + nt * 8 + (lane & 3) * 2;
            float d0 = acc[mt][nt][0], d1 = acc[mt][nt][1];
            float d2 = acc[mt][nt][2], d3 = acc[mt][nt][3];
            if (EPI == 1 || EPI == 2) {
                float b0v = bias[col], b1v = bias[col + 1];
                d0 += b0v; d1 += b1v; d2 += b0v; d3 += b1v;
            }
            if (EPI == 1) {
                d0 = fmaxf(d0, 0.f); d1 = fmaxf(d1, 0.f);
                d2 = fmaxf(d2, 0.f); d3 = fmaxf(d3, 0.f);
                *(uint32_t*)(Chi + (size_t)r0 * N + col) = pack2(d0, d1);
                *(uint32_t*)(Chi + (size_t)(r0 + 8) * N + col) = pack2(d2, d3);
            } else if (EPI == 4) {
                *(uint32_t*)(Chi + (size_t)r0 * N + col) = pack2(d0, d1);
                *(uint32_t*)(Chi + (size_t)(r0 + 8) * N + col) = pack2(d2, d3);
            } else {
                *(float2*)(Cf + (size_t)r0 * N + col) = make_float2(d0, d1);
                *(float2*)(Cf + (size_t)(r0 + 8) * N + col) = make_float2(d2, d3);
            }
        }
    }
}

// ---------------------------------------------------------------------------
// HMMA flash attention (f16x3 QK^T, f16x1 PV, log2-domain softmax with
// f16x2 exponentials: probs computed directly in packed f16 for the PV MMA).
// Block: 128 threads (4 warps), 64-query tile of one (b,h).
// smem: Q hi/lo (16 KB) + 2 stages x (Kh,Kl,Vh) (48 KB) = 64 KB.
// ---------------------------------------------------------------------------
#define ATT_STAGE 24576
#define SMEMB_ATT (16384 + 2 * ATT_STAGE)

__global__ void __launch_bounds__(128) flash_attn_hmma(
    const __half* __restrict__ qkvh, const __half* __restrict__ qkvl,
    __half* __restrict__ ctxh)
{
    extern __shared__ __align__(128) char sm[];
    const uint32_t sb = smem_u32(sm);
    const uint32_t qb = sb;
    const uint32_t kvb = sb + 16384;
    const int tid = threadIdx.x, lane = tid & 31, w = tid >> 5;
    const int bh = blockIdx.y, b = bh >> 4, h = bh & 15;
    const int q0 = blockIdx.x * 64;
    const size_t rowbase = (size_t)b * SS;

    const int lrow = tid >> 1;
    const int lc0 = (tid & 1) * 4;

    {
        const __half* sh = qkvh + (rowbase + q0 + lrow) * (3 * EE) + h * HD + lc0 * 8;
        const __half* sl = qkvl + (rowbase + q0 + lrow) * (3 * EE) + h * HD + lc0 * 8;
#pragma unroll
        for (int c = 0; c < 4; c++) {
            uint32_t d = qb + lrow * 128 + (((lc0 + c) ^ (lrow & 7)) << 4);
            CP_ASYNC16(d, sh + c * 8);
            CP_ASYNC16(d + 8192, sl + c * 8);
        }
    }
    CP_COMMIT();

    auto load_kv = [&](int kt, int buf) {
        size_t grow = (rowbase + kt * 64 + lrow) * (3 * EE);
        const __half* kh = qkvh + grow + EE + h * HD + lc0 * 8;
        const __half* kl = qkvl + grow + EE + h * HD + lc0 * 8;
        const __half* vh = qkvh + grow + 2 * EE + h * HD + lc0 * 8;
        uint32_t d = kvb + buf * ATT_STAGE + lrow * 128;
#pragma unroll
        for (int c = 0; c < 4; c++) {
            uint32_t sw = (((lc0 + c) ^ (lrow & 7)) << 4);
            CP_ASYNC16(d + sw, kh + c * 8);
            CP_ASYNC16(d + 8192 + sw, kl + c * 8);
            CP_ASYNC16(d + 16384 + sw, vh + c * 8);
        }
    };
    load_kv(0, 0); CP_COMMIT();
    CP_WAIT0();
    __syncthreads();

    const int arow = lane & 15, akh = lane >> 4;
    uint32_t qa[2][4][4];
#pragma unroll
    for (int hl = 0; hl < 2; hl++)
#pragma unroll
        for (int kb = 0; kb < 4; kb++) {
            int row = w * 16 + arow;
            uint32_t a = qb + hl * 8192 + row * 128
                       + (((kb * 2 + akh) ^ (row & 7)) << 4);
            ldsm4(qa[hl][kb], a);
        }

    const int brow = ((lane >> 4) << 3) + (lane & 7);
    const int bkh  = (lane >> 3) & 1;
    const int vkey_off = ((lane >> 3) & 1) * 8 + (lane & 7);
    const int vchk_off = lane >> 4;

    float o[8][4] = {};
    float m0 = -1e30f, m1 = -1e30f, l0 = 0.f, l1 = 0.f;

    const int nkt = SS / 64;
    for (int kt = 0; kt < nkt; kt++) {
        const int buf = kt & 1;
        if (kt + 1 < nkt) load_kv(kt + 1, buf ^ 1);
        CP_COMMIT();
        const uint32_t stb = kvb + buf * ATT_STAGE;

        float sf[8][4] = {};
#pragma unroll
        for (int np = 0; np < 4; np++) {
            int rowb = np * 16 + brow;
#pragma unroll
            for (int kb = 0; kb < 4; kb++) {
                uint32_t kfh[4], kfl[4];
                uint32_t sw = (((kb * 2 + bkh) ^ (rowb & 7)) << 4);
                ldsm4(kfh, stb + rowb * 128 + sw);
                ldsm4(kfl, stb + 8192 + rowb * 128 + sw);
#pragma unroll
                for (int e = 0; e < 2; e++) {
                    float* d = sf[2 * np + e];
                    mma_f16(d, qa[0][kb], &kfh[e * 2]);
                    mma_f16(d, qa[0][kb], &kfl[e * 2]);
                    mma_f16(d, qa[1][kb], &kfh[e * 2]);
                }
            }
        }

        // ---- online softmax (log2 domain), probs in packed f16x2 ----
        float mx0 = m0, mx1 = m1;
#pragma unroll
        for (int nt = 0; nt < 8; nt++) {
            mx0 = fmaxf(mx0, fmaxf(sf[nt][0], sf[nt][1]));
            mx1 = fmaxf(mx1, fmaxf(sf[nt][2], sf[nt][3]));
        }
        mx0 = fmaxf(mx0, __shfl_xor_sync(0xffffffffu, mx0, 1));
        mx0 = fmaxf(mx0, __shfl_xor_sync(0xffffffffu, mx0, 2));
        mx1 = fmaxf(mx1, __shfl_xor_sync(0xffffffffu, mx1, 1));
        mx1 = fmaxf(mx1, __shfl_xor_sync(0xffffffffu, mx1, 2));
        float corr0 = ex2(m0 - mx0), corr1 = ex2(m1 - mx1);
        m0 = mx0; m1 = mx1;

        uint32_t p0[8], p1[8];
#pragma unroll
        for (int nt = 0; nt < 8; nt++) {
            p0[nt] = ex2_f16x2(cvt_f16x2(sf[nt][0] - m0, sf[nt][1] - m0));
            p1[nt] = ex2_f16x2(cvt_f16x2(sf[nt][2] - m1, sf[nt][3] - m1));
        }
        // row sums via HADD2 tree, finalized in f32
        uint32_t s0 = hadd2u(hadd2u(hadd2u(p0[0], p0[1]), hadd2u(p0[2], p0[3])),
                             hadd2u(hadd2u(p0[4], p0[5]), hadd2u(p0[6], p0[7])));
        uint32_t s1 = hadd2u(hadd2u(hadd2u(p1[0], p1[1]), hadd2u(p1[2], p1[3])),
                             hadd2u(hadd2u(p1[4], p1[5]), hadd2u(p1[6], p1[7])));
        float2 f0 = __half22float2(*(__half2*)&s0);
        float2 f1 = __half22float2(*(__half2*)&s1);
        float rs0 = f0.x + f0.y;
        float rs1 = f1.x + f1.y;
        rs0 += __shfl_xor_sync(0xffffffffu, rs0, 1);
        rs0 += __shfl_xor_sync(0xffffffffu, rs0, 2);
        rs1 += __shfl_xor_sync(0xffffffffu, rs1, 1);
        rs1 += __shfl_xor_sync(0xffffffffu, rs1, 2);
        l0 = l0 * corr0 + rs0;
        l1 = l1 * corr1 + rs1;
#pragma unroll
        for (int nt = 0; nt < 8; nt++) {
            o[nt][0] *= corr0; o[nt][1] *= corr0;
            o[nt][2] *= corr1; o[nt][3] *= corr1;
        }

        // ---- ctx += P V (probs already packed f16x2) ----
#pragma unroll
        for (int kb2 = 0; kb2 < 4; kb2++) {
            uint32_t pah[4];
            pah[0] = p0[2 * kb2];
            pah[1] = p1[2 * kb2];
            pah[2] = p0[2 * kb2 + 1];
            pah[3] = p1[2 * kb2 + 1];
            int vkey = kb2 * 16 + vkey_off;
#pragma unroll
            for (int np = 0; np < 4; np++) {
                uint32_t vfh[4];
                uint32_t sw = (((np * 2 + vchk_off) ^ (vkey & 7)) << 4);
                ldsm4t(vfh, stb + 16384 + vkey * 128 + sw);
                mma_f16(o[2 * np],     pah, &vfh[0]);
                mma_f16(o[2 * np + 1], pah, &vfh[2]);
            }
        }

        CP_WAIT0();
        __syncthreads();
    }

    const float inv0 = 1.f / l0, inv1 = 1.f / l1;
    const size_t r0 = rowbase + q0 + w * 16 + (lane >> 2);
    const int colb = h * HD + (lane & 3) * 2;
#pragma unroll
    for (int nt = 0; nt < 8; nt++) {
        *(uint32_t*)(ctxh + r0 * EE + colb + nt * 8) =
            pack2(o[nt][0] * inv0, o[nt][1] * inv0);
        *(uint32_t*)(ctxh + (r0 + 8) * EE + colb + nt * 8) =
            pack2(o[nt][2] * inv1, o[nt][3] * inv1);
    }
}

// ---------------------------------------------------------------------------
// Fused residual add + LayerNorm (+ optional f16 output)
// ---------------------------------------------------------------------------
template <int SPLIT>
__global__ void __launch_bounds__(256) add_ln_kernel(
    const float* __restrict__ X, const float* __restrict__ R,
    const float* __restrict__ gam, const float* __restrict__ bet,
    float* __restrict__ out, __half* __restrict__ ohi)
{
    __shared__ float red[8][2];
    __shared__ float s_mu, s_rstd;

    const int row = blockIdx.x;
    const int t = threadIdx.x;
    const size_t base = (size_t)row * EE + t * 4;

    float4 xv = *(const float4*)(X + base);
    float4 rv = *(const float4*)(R + base);
    float v0 = xv.x + rv.x, v1 = xv.y + rv.y;
    float v2 = xv.z + rv.z, v3 = xv.w + rv.w;

    float s  = v0 + v1 + v2 + v3;
    float ss = v0 * v0 + v1 * v1 + v2 * v2 + v3 * v3;
#pragma unroll
    for (int o = 16; o; o >>= 1) {
        s  += __shfl_down_sync(0xffffffffu, s, o);
        ss += __shfl_down_sync(0xffffffffu, ss, o);
    }
    if ((t & 31) == 0) { red[t >> 5][0] = s; red[t >> 5][1] = ss; }
    __syncthreads();
    if (t == 0) {
        float S = 0.f, SSum = 0.f;
#pragma unroll
        for (int i = 0; i < 8; i++) { S += red[i][0]; SSum += red[i][1]; }
        float mu = S * (1.f / EE);
        float var = SSum * (1.f / EE) - mu * mu;
        s_mu = mu;
        s_rstd = rsqrtf(var + 1e-5f);
    }
    __syncthreads();
    const float mu = s_mu, rstd = s_rstd;

    float4 gv = *(const float4*)(gam + t * 4);
    float4 bv = *(const float4*)(bet + t * 4);
    float o0 = (v0 - mu) * rstd * gv.x + bv.x;
    float o1 = (v1 - mu) * rstd * gv.y + bv.y;
    float o2 = (v2 - mu) * rstd * gv.z + bv.z;
    float o3 = (v3 - mu) * rstd * gv.w + bv.w;
    *(float4*)(out + base) = make_float4(o0, o1, o2, o3);

    if (SPLIT) {
        *(uint2*)(ohi + base) = make_uint2(pack2(o0, o1), pack2(o2, o3));
    }
}

// ---------------------------------------------------------------------------
// Launch
// ---------------------------------------------------------------------------
extern "C" void kernel_launch(void* const* d_in, const int* in_sizes, int n_in,
                              void* d_out, int out_size)
{
    const float* x          = (const float*)d_in[0];
    const float* in_proj_w  = (const float*)d_in[1];
    const float* out_proj_w = (const float*)d_in[2];
    const float* ln1_g      = (const float*)d_in[3];
    const float* ln1_b      = (const float*)d_in[4];
    const float* ln2_g      = (const float*)d_in[5];
    const float* ln2_b      = (const float*)d_in[6];
    const float* w1         = (const float*)d_in[7];
    const float* b1         = (const float*)d_in[8];
    const float* w2         = (const float*)d_in[9];
    const float* b2         = (const float*)d_in[10];
    float* out = (float*)d_out;

    float *attnout, *h1, *ff2;
    __half *qkvh, *qkvl, *xh, *xl, *ctxh, *h1h, *ff1h;
    __half *wqkvh, *wqkvl, *wout, *w1c, *w2c;
    cudaGetSymbolAddress((void**)&attnout, g_attnout);
    cudaGetSymbolAddress((void**)&h1,      g_h1);
    cudaGetSymbolAddress((void**)&ff2,     g_ff2);
    cudaGetSymbolAddress((void**)&qkvh,    g_qkvh);
    cudaGetSymbolAddress((void**)&qkvl,    g_qkvl);
    cudaGetSymbolAddress((void**)&xh,      g_xh);
    cudaGetSymbolAddress((void**)&xl,      g_xl);
    cudaGetSymbolAddress((void**)&ctxh,    g_ctxh);
    cudaGetSymbolAddress((void**)&h1h,     g_h1h);
    cudaGetSymbolAddress((void**)&ff1h,    g_ff1h);
    cudaGetSymbolAddress((void**)&wqkvh,   g_wqkvh);
    cudaGetSymbolAddress((void**)&wqkvl,   g_wqkvl);
    cudaGetSymbolAddress((void**)&wout,    g_wout);
    cudaGetSymbolAddress((void**)&w1c,     g_w1);
    cudaGetSymbolAddress((void**)&w2c,     g_w2);

    const int SMEM1 = 2 * 3 * TILE_BYTES;   // 96 KB
    cudaFuncSetAttribute(gemm_qk, cudaFuncAttributeMaxDynamicSharedMemorySize, SMEMB_QK);
    cudaFuncSetAttribute(gemm_hmma<4>, cudaFuncAttributeMaxDynamicSharedMemorySize, SMEM1);
    cudaFuncSetAttribute(gemm_hmma<0>, cudaFuncAttributeMaxDynamicSharedMemorySize, SMEM1);
    cudaFuncSetAttribute(gemm_hmma<1>, cudaFuncAttributeMaxDynamicSharedMemorySize, SMEM1);
    cudaFuncSetAttribute(gemm_hmma<2>, cudaFuncAttributeMaxDynamicSharedMemorySize, SMEM1);
    cudaFuncSetAttribute(flash_attn_hmma, cudaFuncAttributeMaxDynamicSharedMemorySize, SMEMB_ATT);

    dim3 blk(256);

    // --- precision conversions ---
    split_fp32<<<(MM * EE / 8 + 255) / 256, blk>>>(x, xh, xl, MM * EE, 1.f);
    split_wqkv<<<(3 * EE * EE / 8 + 255) / 256, blk>>>(in_proj_w, wqkvh, wqkvl, 3 * EE * EE);
    conv3_fp32<<<((EE * EE + FFD * EE + EE * FFD) / 8 + 255) / 256, blk>>>(
        out_proj_w, wout, EE * EE, w1, w1c, FFD * EE, w2, w2c, EE * FFD);

    // 1a) QK projection (3-term, 2 CTAs/SM) -> f16 hi/lo
    gemm_qk<<<dim3(2 * EE / 64, MM / 128), blk, SMEMB_QK>>>(
        xh, xl, wqkvh, wqkvl, qkvh, qkvl, 3 * EE, EE);
    // 1b) V projection (1-term) -> f16 hi, cols [2E, 3E)
    gemm_hmma<4><<<dim3(EE / 128, MM / 128), blk, SMEM1>>>(
        xh, wqkvh + (size_t)2 * EE * EE, nullptr, nullptr,
        qkvh + 2 * EE, 3 * EE, EE);
    // 2) attention (HMMA, f16x2 exponentials) -> ctx f16
    flash_attn_hmma<<<dim3(SS / 64, BB * HH), 128, SMEMB_ATT>>>(qkvh, qkvl, ctxh);
    // 3) out projection (1-term) -> fp32
    gemm_hmma<0><<<dim3(EE / 128, MM / 128), blk, SMEM1>>>(
        ctxh, wout, nullptr, attnout, nullptr, EE, EE);
    // 4) h1 = LN(x + attnout) -> fp32 + f16
    add_ln_kernel<1><<<MM, blk>>>(x, attnout, ln1_g, ln1_b, h1, h1h);
    // 5) ff1 = relu(h1 @ w1^T + b1) (1-term) -> f16
    gemm_hmma<1><<<dim3(FFD / 128, MM / 128), blk, SMEM1>>>(
        h1h, w1c, b1, nullptr, ff1h, FFD, EE);
    // 6) ff2 = ff1 @ w2^T + b2 (1-term) -> fp32
    gemm_hmma<2><<<dim3(EE / 128, MM / 128), blk, SMEM1>>>(
        ff1h, w2c, b2, ff2, nullptr, EE, FFD);
    // 7) out = LN(h1 + ff2)
    add_ln_kernel<0><<<MM, blk>>>(h1, ff2, ln2_g, ln2_b, out, nullptr);
}